// round 4
// baseline (speedup 1.0000x reference)
#include <cuda_runtime.h>
#include <mma.h>
#include <cstdint>
#include <cstddef>
#include <math.h>

using namespace nvcuda;

// Problem constants
#define Bb 4
#define Ll 4096
#define Dd 2048
#define Hh 32
#define HD 64
#define MTOT (Bb * Ll)   // 16384 rows in all GEMMs

// ---------------------------------------------------------------------------
// Scratch buffers (device globals; no allocation allowed)
// ---------------------------------------------------------------------------
__device__ float g_q[(size_t)Bb * Ll * Dd];
__device__ float g_k[(size_t)Bb * Ll * Dd];
__device__ float g_v[(size_t)Bb * Ll * Dd];
__device__ float g_o2[(size_t)Bb * Ll * Dd];
__device__ float g_cos[Ll * 32];
__device__ float g_sin[Ll * 32];

// ---------------------------------------------------------------------------
// RoPE table: ang[l][i] = l * (1 / 10000^(i/32)), computed in f32 like the ref
// ---------------------------------------------------------------------------
__global__ void rope_table_kernel() {
    int l = blockIdx.x;
    int d = threadIdx.x;            // 0..31
    float p = powf(10000.0f, (float)d * (1.0f / 32.0f));
    float theta = 1.0f / p;
    float ang = (float)l * theta;   // f32 rounding matches reference
    float s, c;
    sincosf(ang, &s, &c);
    g_cos[l * 32 + d] = c;
    g_sin[l * 32 + d] = s;
}

// ---------------------------------------------------------------------------
// TF32 wmma GEMM:  Y[M,N] = X[M,K] @ W[N,K]^T   (no bias)
// Tiles: BM=128, BN=128, BK=16. 256 threads = 8 warps (4x2), warp tile 32x64.
// cp.async double-buffered shared memory.
// ---------------------------------------------------------------------------
#define BM 128
#define BN 128
#define BK 16
#define BKP 20          // padded k-stride (multiple of 4 for wmma ldm)
#define KD 2048
#define ND 2048

__device__ __forceinline__ void cpa16(float* smem, const float* gmem) {
    unsigned a = (unsigned)__cvta_generic_to_shared(smem);
    asm volatile("cp.async.ca.shared.global [%0], [%1], 16;\n" :: "r"(a), "l"(gmem));
}

__device__ __forceinline__ void gemm_prefetch(const float* X, const float* W,
                                              float* As, float* Bs,
                                              int bm, int bn, int k0, int tid) {
    // 512 float4 chunks each for A and B (128 rows x 4 segments)
    for (int c = tid; c < 512; c += 256) {
        int r = c >> 2;
        int s = c & 3;
        cpa16(As + r * BKP + s * 4, X + (size_t)(bm + r) * KD + k0 + s * 4);
        cpa16(Bs + r * BKP + s * 4, W + (size_t)(bn + r) * KD + k0 + s * 4);
    }
}

__global__ void __launch_bounds__(256)
gemm_tn(const float* __restrict__ Xext, const float* __restrict__ W,
        float* __restrict__ Yext, int xsel, int ysel) {
    const float* X = (xsel == 0) ? Xext : (const float*)g_o2;
    float* Y;
    switch (ysel) {
        case 0: Y = g_q; break;
        case 1: Y = g_k; break;
        case 2: Y = g_v; break;
        default: Y = Yext; break;
    }

    __shared__ __align__(16) float As[2][BM * BKP];
    __shared__ __align__(16) float Bs[2][BN * BKP];

    int tid = threadIdx.x;
    int bm = blockIdx.y * BM;
    int bn = blockIdx.x * BN;
    int wid = tid >> 5;
    int wm = (wid >> 1) * 32;   // warp row offset within block tile
    int wn = (wid & 1) * 64;    // warp col offset within block tile

    wmma::fragment<wmma::accumulator, 16, 16, 8, float> acc[2][4];
#pragma unroll
    for (int i = 0; i < 2; i++)
#pragma unroll
        for (int j = 0; j < 4; j++)
            wmma::fill_fragment(acc[i][j], 0.0f);

    const int nIter = KD / BK;   // 128

    gemm_prefetch(X, W, As[0], Bs[0], bm, bn, 0, tid);
    asm volatile("cp.async.commit_group;\n" ::: "memory");
    gemm_prefetch(X, W, As[1], Bs[1], bm, bn, BK, tid);
    asm volatile("cp.async.commit_group;\n" ::: "memory");

    for (int it = 0; it < nIter; ++it) {
        asm volatile("cp.async.wait_group 1;\n" ::: "memory");
        __syncthreads();
        int buf = it & 1;

#pragma unroll
        for (int ks = 0; ks < 2; ++ks) {
            wmma::fragment<wmma::matrix_a, 16, 16, 8, wmma::precision::tf32, wmma::row_major> af[2];
            wmma::fragment<wmma::matrix_b, 16, 16, 8, wmma::precision::tf32, wmma::col_major> bf[4];
#pragma unroll
            for (int i = 0; i < 2; i++) {
                wmma::load_matrix_sync(af[i], &As[buf][(wm + i * 16) * BKP + ks * 8], BKP);
#pragma unroll
                for (int t = 0; t < af[i].num_elements; t++)
                    af[i].x[t] = wmma::__float_to_tf32(af[i].x[t]);
            }
#pragma unroll
            for (int j = 0; j < 4; j++) {
                wmma::load_matrix_sync(bf[j], &Bs[buf][(wn + j * 16) * BKP + ks * 8], BKP);
#pragma unroll
                for (int t = 0; t < bf[j].num_elements; t++)
                    bf[j].x[t] = wmma::__float_to_tf32(bf[j].x[t]);
            }
#pragma unroll
            for (int i = 0; i < 2; i++)
#pragma unroll
                for (int j = 0; j < 4; j++)
                    wmma::mma_sync(acc[i][j], af[i], bf[j], acc[i][j]);
        }
        __syncthreads();

        if (it + 2 < nIter)
            gemm_prefetch(X, W, As[buf], Bs[buf], bm, bn, (it + 2) * BK, tid);
        asm volatile("cp.async.commit_group;\n" ::: "memory");
    }

#pragma unroll
    for (int i = 0; i < 2; i++)
#pragma unroll
        for (int j = 0; j < 4; j++)
            wmma::store_matrix_sync(Y + (size_t)(bm + wm + i * 16) * ND + bn + wn + j * 16,
                                    acc[i][j], ND, wmma::mem_row_major);
}

// ---------------------------------------------------------------------------
// Attention over heads axis, fused bias + RoPE, packed f32x2 math.
// One warp per (b,l). lane = head h. Writes directly into the reshuffled
// layout:   o2[b][h*128 + l/32][(l%32)*64 + d]
// ---------------------------------------------------------------------------
union F2U { float2 f; unsigned long long u; };

__device__ __forceinline__ void ffma2(F2U& acc, F2U a, F2U b) {
    asm("fma.rn.f32x2 %0, %1, %2, %0;" : "+l"(acc.u) : "l"(a.u), "l"(b.u));
}

__global__ void __launch_bounds__(64)
attn_kernel(const float* __restrict__ bq, const float* __restrict__ bk,
            const float* __restrict__ bv) {
    __shared__ __align__(16) float ksh[2][32][64];
    __shared__ __align__(16) float vsh[2][32][64];
    __shared__ float csh[2][32];
    __shared__ float ssh[2][32];

    int w = threadIdx.x >> 5;
    int lane = threadIdx.x & 31;
    int pos = blockIdx.x * 2 + w;       // b*L + l
    int l = pos & (Ll - 1);
    int b = pos >> 12;
    size_t base = (size_t)pos * Dd;

    csh[w][lane] = g_cos[l * 32 + lane];
    ssh[w][lane] = g_sin[l * 32 + lane];
    __syncwarp();

    // --- stage K (bias + rope) and V (bias) rows into shared; lane loads row 'lane'
    {
        const float4* kr4 = (const float4*)(g_k + base + lane * HD);
        const float4* vr4 = (const float4*)(g_v + base + lane * HD);
        const float4* bk4 = (const float4*)(bk + lane * HD);
        const float4* bv4 = (const float4*)(bv + lane * HD);
        float4* kdst = (float4*)&ksh[w][lane][0];
        float4* vdst = (float4*)&vsh[w][lane][0];
#pragma unroll
        for (int j = 0; j < 8; j++) {
            float4 lo = kr4[j], hi = kr4[j + 8];
            float4 blo = bk4[j], bhi = bk4[j + 8];
            lo.x += blo.x; lo.y += blo.y; lo.z += blo.z; lo.w += blo.w;
            hi.x += bhi.x; hi.y += bhi.y; hi.z += bhi.z; hi.w += bhi.w;
            float c0 = csh[w][4 * j + 0], c1 = csh[w][4 * j + 1];
            float c2 = csh[w][4 * j + 2], c3 = csh[w][4 * j + 3];
            float s0 = ssh[w][4 * j + 0], s1 = ssh[w][4 * j + 1];
            float s2 = ssh[w][4 * j + 2], s3 = ssh[w][4 * j + 3];
            float4 olo, ohi;
            olo.x = lo.x * c0 - hi.x * s0;  ohi.x = hi.x * c0 + lo.x * s0;
            olo.y = lo.y * c1 - hi.y * s1;  ohi.y = hi.y * c1 + lo.y * s1;
            olo.z = lo.z * c2 - hi.z * s2;  ohi.z = hi.z * c2 + lo.z * s2;
            olo.w = lo.w * c3 - hi.w * s3;  ohi.w = hi.w * c3 + lo.w * s3;
            kdst[j] = olo;
            kdst[j + 8] = ohi;

            float4 v0 = vr4[j], bb0 = bv4[j];
            v0.x += bb0.x; v0.y += bb0.y; v0.z += bb0.z; v0.w += bb0.w;
            vdst[j] = v0;
            float4 v1 = vr4[j + 8], bb1 = bv4[j + 8];
            v1.x += bb1.x; v1.y += bb1.y; v1.z += bb1.z; v1.w += bb1.w;
            vdst[j + 8] = v1;
        }
    }

    // --- q row (bias + rope) into registers
    float qv[64];
    {
        const float4* qr4 = (const float4*)(g_q + base + lane * HD);
        const float4* bq4 = (const float4*)(bq + lane * HD);
#pragma unroll
        for (int j = 0; j < 8; j++) {
            float4 lo = qr4[j], hi = qr4[j + 8];
            float4 blo = bq4[j], bhi = bq4[j + 8];
            lo.x += blo.x; lo.y += blo.y; lo.z += blo.z; lo.w += blo.w;
            hi.x += bhi.x; hi.y += bhi.y; hi.z += bhi.z; hi.w += bhi.w;
            float c0 = csh[w][4 * j + 0], c1 = csh[w][4 * j + 1];
            float c2 = csh[w][4 * j + 2], c3 = csh[w][4 * j + 3];
            float s0 = ssh[w][4 * j + 0], s1 = ssh[w][4 * j + 1];
            float s2 = ssh[w][4 * j + 2], s3 = ssh[w][4 * j + 3];
            qv[4 * j + 0]      = lo.x * c0 - hi.x * s0;
            qv[4 * j + 1]      = lo.y * c1 - hi.y * s1;
            qv[4 * j + 2]      = lo.z * c2 - hi.z * s2;
            qv[4 * j + 3]      = lo.w * c3 - hi.w * s3;
            qv[32 + 4 * j + 0] = hi.x * c0 + lo.x * s0;
            qv[32 + 4 * j + 1] = hi.y * c1 + lo.y * s1;
            qv[32 + 4 * j + 2] = hi.z * c2 + lo.z * s2;
            qv[32 + 4 * j + 3] = hi.w * c3 + lo.w * s3;
        }
    }
    __syncwarp();

    int h = lane;

    // --- scores (causal: g <= h), packed f32x2 FMA
    float sc[32];
    float mx = -1e30f;
#pragma unroll
    for (int g = 0; g < 32; ++g) {
        if (g <= h) {
            F2U acc; acc.f = make_float2(0.0f, 0.0f);
            const float4* kr = (const float4*)&ksh[w][g][0];
#pragma unroll
            for (int j = 0; j < 16; j++) {
                float4 kk = kr[j];
                F2U a1, b1, a2, b2;
                a1.f = make_float2(qv[4 * j + 0], qv[4 * j + 1]);
                b1.f = make_float2(kk.x, kk.y);
                ffma2(acc, a1, b1);
                a2.f = make_float2(qv[4 * j + 2], qv[4 * j + 3]);
                b2.f = make_float2(kk.z, kk.w);
                ffma2(acc, a2, b2);
            }
            float s_ = (acc.f.x + acc.f.y) * 0.125f;   // 1/sqrt(64)
            sc[g] = s_;
            mx = fmaxf(mx, s_);
        }
    }

    // --- softmax (unnormalized; fold 1/denom at the end)
    float denom = 0.0f;
#pragma unroll
    for (int g = 0; g < 32; ++g) {
        if (g <= h) {
            float e = expf(sc[g] - mx);
            sc[g] = e;
            denom += e;
        }
    }
    float inv = 1.0f / denom;

    // --- out = attn @ V
    F2U ov[32];
#pragma unroll
    for (int j = 0; j < 32; j++) ov[j].f = make_float2(0.0f, 0.0f);
#pragma unroll
    for (int g = 0; g < 32; ++g) {
        if (g <= h) {
            F2U aa; aa.f = make_float2(sc[g], sc[g]);
            const float4* vr = (const float4*)&vsh[w][g][0];
#pragma unroll
            for (int j = 0; j < 16; j++) {
                float4 vv = vr[j];
                F2U b1, b2;
                b1.f = make_float2(vv.x, vv.y);
                b2.f = make_float2(vv.z, vv.w);
                ffma2(ov[2 * j], aa, b1);
                ffma2(ov[2 * j + 1], aa, b2);
            }
        }
    }

    // --- store into reshuffled layout for the output GEMM
    float* orow = g_o2 + ((size_t)(b * 4096 + h * 128 + (l >> 5)) * Dd + (l & 31) * HD);
    float4* orow4 = (float4*)orow;
#pragma unroll
    for (int j = 0; j < 16; j++) {
        float4 t;
        t.x = ov[2 * j].f.x * inv;
        t.y = ov[2 * j].f.y * inv;
        t.z = ov[2 * j + 1].f.x * inv;
        t.w = ov[2 * j + 1].f.y * inv;
        orow4[j] = t;
    }
}

// ---------------------------------------------------------------------------
// Final bias add on d_out
// ---------------------------------------------------------------------------
__global__ void __launch_bounds__(256)
bias_add_kernel(float* __restrict__ y, const float* __restrict__ b) {
    int i = blockIdx.x * 256 + threadIdx.x;      // over float4 elements
    float4* y4 = (float4*)y;
    const float4* b4 = (const float4*)b;
    float4 t = y4[i];
    float4 bb = b4[i & 511];                      // D/4 = 512
    t.x += bb.x; t.y += bb.y; t.z += bb.z; t.w += bb.w;
    y4[i] = t;
}

// ---------------------------------------------------------------------------
// Launch
// ---------------------------------------------------------------------------
extern "C" void kernel_launch(void* const* d_in, const int* in_sizes, int n_in,
                              void* d_out, int out_size) {
    const float* x  = (const float*)d_in[0];
    const float* Wq = (const float*)d_in[1];
    const float* bq = (const float*)d_in[2];
    const float* Wk = (const float*)d_in[3];
    const float* bk = (const float*)d_in[4];
    const float* Wv = (const float*)d_in[5];
    const float* bv = (const float*)d_in[6];
    const float* Wo = (const float*)d_in[7];
    const float* bo = (const float*)d_in[8];
    float* out = (float*)d_out;

    (void)in_sizes; (void)n_in; (void)out_size;

    // RoPE cos/sin table
    rope_table_kernel<<<Ll, 32>>>();

    dim3 gg(ND / BN, MTOT / BM);   // (16, 128)
    // Q, K, V projections (bias deferred into attention kernel)
    gemm_tn<<<gg, 256>>>(x, Wq, nullptr, 0, 0);
    gemm_tn<<<gg, 256>>>(x, Wk, nullptr, 0, 1);
    gemm_tn<<<gg, 256>>>(x, Wv, nullptr, 0, 2);

    // Attention (fused bias + rope) -> reshuffled o2
    attn_kernel<<<(Bb * Ll) / 2, 64>>>(bq, bk, bv);

    // Output projection from o2 into d_out, then bias
    gemm_tn<<<gg, 256>>>(nullptr, Wo, out, 1, 3);
    bias_add_kernel<<<(MTOT * Dd) / (4 * 256), 256>>>(out, bo);
}

// round 7
// speedup vs baseline: 4.0062x; 4.0062x over previous
#include <cuda_runtime.h>
#include <cuda_fp16.h>
#include <mma.h>
#include <cstdint>
#include <cstddef>
#include <math.h>

using namespace nvcuda;

// Problem constants
#define Bb 4
#define Ll 4096
#define Dd 2048
#define HD 64
#define MTOT (Bb * Ll)   // 16384

// ---------------------------------------------------------------------------
// Scratch (device globals; no allocation allowed)
// ---------------------------------------------------------------------------
__device__ __half g_x16[(size_t)MTOT * Dd];        // fp16 X
__device__ __half g_w16[4][(size_t)Dd * Dd];       // fp16 Wq/Wk/Wv/Wo
__device__ __half g_o16[(size_t)MTOT * Dd];        // fp16 attention output (reshuffled)
__device__ float  g_q[(size_t)MTOT * Dd];
__device__ float  g_k[(size_t)MTOT * Dd];
__device__ float  g_v[(size_t)MTOT * Dd];
__device__ float  g_cos[Ll * 32];
__device__ float  g_sin[Ll * 32];

// ---------------------------------------------------------------------------
// RoPE table
// ---------------------------------------------------------------------------
__global__ void rope_table_kernel() {
    int l = blockIdx.x;
    int d = threadIdx.x;
    float p = powf(10000.0f, (float)d * (1.0f / 32.0f));
    float theta = 1.0f / p;
    float ang = (float)l * theta;
    float s, c;
    sincosf(ang, &s, &c);
    g_cos[l * 32 + d] = c;
    g_sin[l * 32 + d] = s;
}

// ---------------------------------------------------------------------------
// Convert f32 -> fp16 (RN), one pass. dsel: 0 -> X, 1..4 -> W[dsel-1]
// ---------------------------------------------------------------------------
__global__ void __launch_bounds__(256)
to_fp16_kernel(const float* __restrict__ src, int dsel) {
    __half* dst = (dsel == 0) ? g_x16 : g_w16[dsel - 1];
    size_t i = (size_t)blockIdx.x * 256 + threadIdx.x;   // index over float4 groups
    float4 v = ((const float4*)src)[i];
    __half2 h0 = __floats2half2_rn(v.x, v.y);
    __half2 h1 = __floats2half2_rn(v.z, v.w);
    ((__half2*)dst)[2 * i]     = h0;
    ((__half2*)dst)[2 * i + 1] = h1;
}

// ---------------------------------------------------------------------------
// FP16 wmma GEMM:  Y[M,N] = A[M,K] @ W[N,K]^T   (f32 accumulate/output)
// CTA tile 128x256x32, 8 warps (2M x 4N), warp tile 64x64.
// 4 smem buffers, 3-deep cp.async pipeline, always-commit.
// ---------------------------------------------------------------------------
#define BM 128
#define BN 256
#define BK 32
#define BKP 40                         // padded row stride in halves (80 B)
#define STGH ((BM + BN) * BKP)         // halves per stage = 15360 (30720 B)
#define NIT (Dd / BK)                  // 64
#define DYN_SMEM (4 * STGH * 2)        // 122880 bytes

__device__ __forceinline__ void cpa16(const __half* smem, const __half* gmem) {
    unsigned a = (unsigned)__cvta_generic_to_shared(smem);
    asm volatile("cp.async.cg.shared.global [%0], [%1], 16;\n" :: "r"(a), "l"(gmem));
}

__device__ __forceinline__ void load_stage(const __half* __restrict__ A,
                                           const __half* __restrict__ W,
                                           __half* s, int bm, int bn,
                                           int k0, int tid) {
#pragma unroll
    for (int i = 0; i < 2; i++) {                 // A: 128 rows x 4 chunks = 512
        int c = tid + i * 256;
        int r = c >> 2, sg = c & 3;
        cpa16(s + r * BKP + sg * 8, A + (size_t)(bm + r) * Dd + k0 + sg * 8);
    }
#pragma unroll
    for (int i = 0; i < 4; i++) {                 // B: 256 rows x 4 chunks = 1024
        int c = tid + i * 256;
        int r = c >> 2, sg = c & 3;
        cpa16(s + BM * BKP + r * BKP + sg * 8, W + (size_t)(bn + r) * Dd + k0 + sg * 8);
    }
}

__global__ void __launch_bounds__(256, 1)
gemm_fp16(int asel, int bsel, float* __restrict__ Yext, int ysel) {
    const __half* A  = (asel == 0) ? g_x16 : g_o16;
    const __half* Bw = g_w16[bsel];
    float* Y;
    switch (ysel) {
        case 0: Y = g_q; break;
        case 1: Y = g_k; break;
        case 2: Y = g_v; break;
        default: Y = Yext; break;
    }

    extern __shared__ __align__(16) __half smem[];

    int tid = threadIdx.x;
    int bm = blockIdx.y * BM;
    int bn = blockIdx.x * BN;
    int wid = tid >> 5;
    int wm = (wid & 1) * 64;        // warp M offset (2 warps in M)
    int wn = (wid >> 1) * 64;       // warp N offset (4 warps in N)

    wmma::fragment<wmma::accumulator, 16, 16, 16, float> acc[4][4];
#pragma unroll
    for (int i = 0; i < 4; i++)
#pragma unroll
        for (int j = 0; j < 4; j++)
            wmma::fill_fragment(acc[i][j], 0.0f);

    // Prologue: stages 0..2
#pragma unroll
    for (int p = 0; p < 3; p++) {
        load_stage(A, Bw, smem + p * STGH, bm, bn, p * BK, tid);
        asm volatile("cp.async.commit_group;" ::: "memory");
    }

    for (int it = 0; it < NIT; ++it) {
        asm volatile("cp.async.wait_group 2;" ::: "memory");
        __syncthreads();

        const __half* sa = smem + (it & 3) * STGH;
        const __half* sb = sa + BM * BKP;

#pragma unroll
        for (int kf = 0; kf < 2; ++kf) {
            wmma::fragment<wmma::matrix_a, 16, 16, 16, __half, wmma::row_major> af[4];
            wmma::fragment<wmma::matrix_b, 16, 16, 16, __half, wmma::col_major> bf[4];
#pragma unroll
            for (int i = 0; i < 4; i++)
                wmma::load_matrix_sync(af[i], sa + (wm + i * 16) * BKP + kf * 16, BKP);
#pragma unroll
            for (int j = 0; j < 4; j++)
                wmma::load_matrix_sync(bf[j], sb + (wn + j * 16) * BKP + kf * 16, BKP);
#pragma unroll
            for (int i = 0; i < 4; i++)
#pragma unroll
                for (int j = 0; j < 4; j++)
                    wmma::mma_sync(acc[i][j], af[i], bf[j], acc[i][j]);
        }

        int L = it + 3;
        if (L < NIT)
            load_stage(A, Bw, smem + (L & 3) * STGH, bm, bn, L * BK, tid);
        asm volatile("cp.async.commit_group;" ::: "memory");   // always commit
    }

    // Epilogue: f32 store
#pragma unroll
    for (int i = 0; i < 4; i++)
#pragma unroll
        for (int j = 0; j < 4; j++)
            wmma::store_matrix_sync(Y + (size_t)(bm + wm + i * 16) * Dd + bn + wn + j * 16,
                                    acc[i][j], Dd, wmma::mem_row_major);
}

// ---------------------------------------------------------------------------
// Attention over heads axis, fused bias + RoPE, packed f32x2 math.
// One warp per (b,l). lane = head h. Output -> fp16, reshuffled layout:
//   o16[b][h*128 + l/32][(l%32)*64 + d]  so the output GEMM reads it row-major.
// ---------------------------------------------------------------------------
union F2U { float2 f; unsigned long long u; };

__device__ __forceinline__ void ffma2(F2U& acc, F2U a, F2U b) {
    asm("fma.rn.f32x2 %0, %1, %2, %0;" : "+l"(acc.u) : "l"(a.u), "l"(b.u));
}

__global__ void __launch_bounds__(64)
attn_kernel(const float* __restrict__ bq, const float* __restrict__ bk,
            const float* __restrict__ bv) {
    __shared__ __align__(16) float ksh[2][32][64];
    __shared__ __align__(16) float vsh[2][32][64];
    __shared__ float csh[2][32];
    __shared__ float ssh[2][32];

    int w = threadIdx.x >> 5;
    int lane = threadIdx.x & 31;
    int pos = blockIdx.x * 2 + w;
    int l = pos & (Ll - 1);
    int b = pos >> 12;
    size_t base = (size_t)pos * Dd;

    csh[w][lane] = g_cos[l * 32 + lane];
    ssh[w][lane] = g_sin[l * 32 + lane];
    __syncwarp();

    {
        const float4* kr4 = (const float4*)(g_k + base + lane * HD);
        const float4* vr4 = (const float4*)(g_v + base + lane * HD);
        const float4* bk4 = (const float4*)(bk + lane * HD);
        const float4* bv4 = (const float4*)(bv + lane * HD);
        float4* kdst = (float4*)&ksh[w][lane][0];
        float4* vdst = (float4*)&vsh[w][lane][0];
#pragma unroll
        for (int j = 0; j < 8; j++) {
            float4 lo = kr4[j], hi = kr4[j + 8];
            float4 blo = bk4[j], bhi = bk4[j + 8];
            lo.x += blo.x; lo.y += blo.y; lo.z += blo.z; lo.w += blo.w;
            hi.x += bhi.x; hi.y += bhi.y; hi.z += bhi.z; hi.w += bhi.w;
            float c0 = csh[w][4 * j + 0], c1 = csh[w][4 * j + 1];
            float c2 = csh[w][4 * j + 2], c3 = csh[w][4 * j + 3];
            float s0 = ssh[w][4 * j + 0], s1 = ssh[w][4 * j + 1];
            float s2 = ssh[w][4 * j + 2], s3 = ssh[w][4 * j + 3];
            float4 olo, ohi;
            olo.x = lo.x * c0 - hi.x * s0;  ohi.x = hi.x * c0 + lo.x * s0;
            olo.y = lo.y * c1 - hi.y * s1;  ohi.y = hi.y * c1 + lo.y * s1;
            olo.z = lo.z * c2 - hi.z * s2;  ohi.z = hi.z * c2 + lo.z * s2;
            olo.w = lo.w * c3 - hi.w * s3;  ohi.w = hi.w * c3 + lo.w * s3;
            kdst[j] = olo;
            kdst[j + 8] = ohi;

            float4 v0 = vr4[j], bb0 = bv4[j];
            v0.x += bb0.x; v0.y += bb0.y; v0.z += bb0.z; v0.w += bb0.w;
            vdst[j] = v0;
            float4 v1 = vr4[j + 8], bb1 = bv4[j + 8];
            v1.x += bb1.x; v1.y += bb1.y; v1.z += bb1.z; v1.w += bb1.w;
            vdst[j + 8] = v1;
        }
    }

    float qv[64];
    {
        const float4* qr4 = (const float4*)(g_q + base + lane * HD);
        const float4* bq4 = (const float4*)(bq + lane * HD);
#pragma unroll
        for (int j = 0; j < 8; j++) {
            float4 lo = qr4[j], hi = qr4[j + 8];
            float4 blo = bq4[j], bhi = bq4[j + 8];
            lo.x += blo.x; lo.y += blo.y; lo.z += blo.z; lo.w += blo.w;
            hi.x += bhi.x; hi.y += bhi.y; hi.z += bhi.z; hi.w += bhi.w;
            float c0 = csh[w][4 * j + 0], c1 = csh[w][4 * j + 1];
            float c2 = csh[w][4 * j + 2], c3 = csh[w][4 * j + 3];
            float s0 = ssh[w][4 * j + 0], s1 = ssh[w][4 * j + 1];
            float s2 = ssh[w][4 * j + 2], s3 = ssh[w][4 * j + 3];
            qv[4 * j + 0]      = lo.x * c0 - hi.x * s0;
            qv[4 * j + 1]      = lo.y * c1 - hi.y * s1;
            qv[4 * j + 2]      = lo.z * c2 - hi.z * s2;
            qv[4 * j + 3]      = lo.w * c3 - hi.w * s3;
            qv[32 + 4 * j + 0] = hi.x * c0 + lo.x * s0;
            qv[32 + 4 * j + 1] = hi.y * c1 + lo.y * s1;
            qv[32 + 4 * j + 2] = hi.z * c2 + lo.z * s2;
            qv[32 + 4 * j + 3] = hi.w * c3 + lo.w * s3;
        }
    }
    __syncwarp();

    int h = lane;

    float sc[32];
    float mx = -1e30f;
#pragma unroll
    for (int g = 0; g < 32; ++g) {
        if (g <= h) {
            F2U acc; acc.f = make_float2(0.0f, 0.0f);
            const float4* kr = (const float4*)&ksh[w][g][0];
#pragma unroll
            for (int j = 0; j < 16; j++) {
                float4 kk = kr[j];
                F2U a1, b1, a2, b2;
                a1.f = make_float2(qv[4 * j + 0], qv[4 * j + 1]);
                b1.f = make_float2(kk.x, kk.y);
                ffma2(acc, a1, b1);
                a2.f = make_float2(qv[4 * j + 2], qv[4 * j + 3]);
                b2.f = make_float2(kk.z, kk.w);
                ffma2(acc, a2, b2);
            }
            float s_ = (acc.f.x + acc.f.y) * 0.125f;   // 1/sqrt(64)
            sc[g] = s_;
            mx = fmaxf(mx, s_);
        }
    }

    float denom = 0.0f;
#pragma unroll
    for (int g = 0; g < 32; ++g) {
        if (g <= h) {
            float e = expf(sc[g] - mx);
            sc[g] = e;
            denom += e;
        }
    }
    float inv = 1.0f / denom;

    F2U ov[32];
#pragma unroll
    for (int j = 0; j < 32; j++) ov[j].f = make_float2(0.0f, 0.0f);
#pragma unroll
    for (int g = 0; g < 32; ++g) {
        if (g <= h) {
            F2U aa; aa.f = make_float2(sc[g], sc[g]);
            const float4* vr = (const float4*)&vsh[w][g][0];
#pragma unroll
            for (int j = 0; j < 16; j++) {
                float4 vv = vr[j];
                F2U b1, b2;
                b1.f = make_float2(vv.x, vv.y);
                b2.f = make_float2(vv.z, vv.w);
                ffma2(ov[2 * j], aa, b1);
                ffma2(ov[2 * j + 1], aa, b2);
            }
        }
    }

    // Store fp16 into reshuffled layout for the output GEMM (16B stores)
    __half* orow = g_o16 + ((size_t)(b * 4096 + h * 128 + (l >> 5)) * Dd + (l & 31) * HD);
    uint4* orow16 = (uint4*)orow;
#pragma unroll
    for (int j = 0; j < 8; j++) {      // 8 x (8 halves)
        union { __half2 h[4]; uint4 u; } pk;
        pk.h[0] = __floats2half2_rn(ov[4 * j + 0].f.x * inv, ov[4 * j + 0].f.y * inv);
        pk.h[1] = __floats2half2_rn(ov[4 * j + 1].f.x * inv, ov[4 * j + 1].f.y * inv);
        pk.h[2] = __floats2half2_rn(ov[4 * j + 2].f.x * inv, ov[4 * j + 2].f.y * inv);
        pk.h[3] = __floats2half2_rn(ov[4 * j + 3].f.x * inv, ov[4 * j + 3].f.y * inv);
        orow16[j] = pk.u;
    }
}

// ---------------------------------------------------------------------------
// Final bias add on d_out
// ---------------------------------------------------------------------------
__global__ void __launch_bounds__(256)
bias_add_kernel(float* __restrict__ y, const float* __restrict__ b) {
    int i = blockIdx.x * 256 + threadIdx.x;
    float4* y4 = (float4*)y;
    const float4* b4 = (const float4*)b;
    float4 t = y4[i];
    float4 bb = b4[i & 511];
    t.x += bb.x; t.y += bb.y; t.z += bb.z; t.w += bb.w;
    y4[i] = t;
}

// ---------------------------------------------------------------------------
// Launch
// ---------------------------------------------------------------------------
extern "C" void kernel_launch(void* const* d_in, const int* in_sizes, int n_in,
                              void* d_out, int out_size) {
    const float* x  = (const float*)d_in[0];
    const float* Wq = (const float*)d_in[1];
    const float* bq = (const float*)d_in[2];
    const float* Wk = (const float*)d_in[3];
    const float* bk = (const float*)d_in[4];
    const float* Wv = (const float*)d_in[5];
    const float* bv = (const float*)d_in[6];
    const float* Wo = (const float*)d_in[7];
    const float* bo = (const float*)d_in[8];
    float* out = (float*)d_out;

    (void)in_sizes; (void)n_in; (void)out_size;

    cudaFuncSetAttribute(gemm_fp16, cudaFuncAttributeMaxDynamicSharedMemorySize, DYN_SMEM);

    rope_table_kernel<<<Ll, 32>>>();

    // One-time fp16 conversion of X and the four weight matrices
    to_fp16_kernel<<<(MTOT * Dd) / (4 * 256), 256>>>(x, 0);
    to_fp16_kernel<<<(Dd * Dd) / (4 * 256), 256>>>(Wq, 1);
    to_fp16_kernel<<<(Dd * Dd) / (4 * 256), 256>>>(Wk, 2);
    to_fp16_kernel<<<(Dd * Dd) / (4 * 256), 256>>>(Wv, 3);
    to_fp16_kernel<<<(Dd * Dd) / (4 * 256), 256>>>(Wv, 3);
    to_fp16_kernel<<<(Dd * Dd) / (4 * 256), 256>>>(Wo, 4);

    dim3 gg(Dd / BN, MTOT / BM);   // (8, 128)
    gemm_fp16<<<gg, 256, DYN_SMEM>>>(0, 0, nullptr, 0);   // Q
    gemm_fp16<<<gg, 256, DYN_SMEM>>>(0, 1, nullptr, 1);   // K
    gemm_fp16<<<gg, 256, DYN_SMEM>>>(0, 2, nullptr, 2);   // V

    attn_kernel<<<(Bb * Ll) / 2, 64>>>(bq, bk, bv);

    gemm_fp16<<<gg, 256, DYN_SMEM>>>(1, 3, out, 3);       // O projection
    bias_add_kernel<<<(MTOT * Dd) / (4 * 256), 256>>>(out, bo);
}